// round 1
// baseline (speedup 1.0000x reference)
#include <cuda_runtime.h>
#include <cstdint>

#define TT 512
#define BB 256
#define HH 1024
#define KK 1024
#define NB2 128   // phase-2 persistent blocks (<= 148 SMs, co-resident)

// Scratch: ping-pong hidden state (2 MB). Device globals are allowed.
__device__ float g_h[2 * BB * HH];
__device__ unsigned g_count;   // zero-init, returns to zero after every barrier
__device__ unsigned g_gen;     // monotone generation counter (wrap-safe compares)

__device__ __forceinline__ float tanh_fast(float x) {
    // exact identity tanh(x) = 1 - 2/(e^{2x}+1); __expf rel err ~4e-7.
    float e = __expf(2.0f * x);
    return 1.0f - 2.0f / (e + 1.0f);
}

__device__ __forceinline__ void grid_sync(unsigned base, unsigned gen, unsigned nb)
{
    __syncthreads();
    if (threadIdx.x == 0) {
        const unsigned target = base + gen;
        __threadfence();
        unsigned a = atomicAdd(&g_count, 1u);
        if (a == nb - 1u) {
            g_count = 0u;
            __threadfence();
            atomicExch(&g_gen, target);
        } else {
            while ((int)(*(volatile unsigned*)&g_gen - target) < 0) {
                __nanosleep(64);
            }
        }
        __threadfence();
    }
    __syncthreads();
}

// ---------------------------------------------------------------------------
// Phase 1: XP[m][j] = bx[j] + sum_k X[m][k] * Wx[j][k]
// M = TT*BB = 131072, N = HH = 1024, K = 1024. Tile 64x64, BK=32, 256 thr,
// thread tile 4x4 (j strided by 16 for conflict-free LDS.128).
// ---------------------------------------------------------------------------
__global__ void __launch_bounds__(256, 2) xproj_kernel(
    const float* __restrict__ X, const float* __restrict__ Wx,
    const float* __restrict__ bx, float* __restrict__ XP)
{
    __shared__ float Xs[2][64][36];
    __shared__ float Ws[2][64][36];

    const int tid = threadIdx.x;
    const int m0 = blockIdx.y * 64;
    const int j0 = blockIdx.x * 64;
    const int ty = tid >> 4;     // 0..15 (m)
    const int tx = tid & 15;     // 0..15 (j)

    const int lr = tid >> 3;     // loader row 0..31
    const int ls = tid & 7;      // loader seg 0..7 (float4)

    const float* Xb = X + (size_t)m0 * KK;
    const float* Wb = Wx + (size_t)j0 * KK;

    float4 x0, x1, w0, w1;
    {
        const float* px = Xb + (size_t)lr * KK + ls * 4;
        x0 = *(const float4*)px;
        x1 = *(const float4*)(px + (size_t)32 * KK);
        const float* pw = Wb + (size_t)lr * KK + ls * 4;
        w0 = *(const float4*)pw;
        w1 = *(const float4*)(pw + (size_t)32 * KK);
    }

    float acc[4][4];
#pragma unroll
    for (int r = 0; r < 4; ++r)
#pragma unroll
        for (int q = 0; q < 4; ++q) acc[r][q] = 0.0f;

#pragma unroll 1
    for (int c = 0; c < KK / 32; ++c) {
        const int buf = c & 1;
        *(float4*)&Xs[buf][lr][ls * 4]      = x0;
        *(float4*)&Xs[buf][lr + 32][ls * 4] = x1;
        *(float4*)&Ws[buf][lr][ls * 4]      = w0;
        *(float4*)&Ws[buf][lr + 32][ls * 4] = w1;
        __syncthreads();

        if (c + 1 < KK / 32) {
            const int kn = (c + 1) * 32;
            const float* px = Xb + (size_t)lr * KK + kn + ls * 4;
            x0 = *(const float4*)px;
            x1 = *(const float4*)(px + (size_t)32 * KK);
            const float* pw = Wb + (size_t)lr * KK + kn + ls * 4;
            w0 = *(const float4*)pw;
            w1 = *(const float4*)(pw + (size_t)32 * KK);
        }

#pragma unroll
        for (int kk = 0; kk < 8; ++kk) {
            float4 a[4], w[4];
#pragma unroll
            for (int r = 0; r < 4; ++r)
                a[r] = *(const float4*)&Xs[buf][ty * 4 + r][kk * 4];
#pragma unroll
            for (int q = 0; q < 4; ++q)
                w[q] = *(const float4*)&Ws[buf][tx + 16 * q][kk * 4];
#pragma unroll
            for (int r = 0; r < 4; ++r)
#pragma unroll
                for (int q = 0; q < 4; ++q) {
                    acc[r][q] = fmaf(a[r].x, w[q].x, acc[r][q]);
                    acc[r][q] = fmaf(a[r].y, w[q].y, acc[r][q]);
                    acc[r][q] = fmaf(a[r].z, w[q].z, acc[r][q]);
                    acc[r][q] = fmaf(a[r].w, w[q].w, acc[r][q]);
                }
        }
    }

    const int mbase = m0 + ty * 4;
#pragma unroll
    for (int q = 0; q < 4; ++q) {
        const int j = j0 + tx + 16 * q;
        const float bj = bx[j];
#pragma unroll
        for (int r = 0; r < 4; ++r)
            XP[(size_t)(mbase + r) * HH + j] = acc[r][q] + bj;
    }
}

// ---------------------------------------------------------------------------
// Phase 2: persistent RNN scan. 128 blocks x 128 threads.
// Block (bt, jt) owns output tile h[b0:b0+64][j0:j0+32] for every timestep.
// Thread tile 4x4 (b rows tbq*4+r, j cols tjj+8q). Double-buffered smem.
// h state ping-pongs in g_h; xp lives in h_all (d_out) and is overwritten
// in-place by h_t. Grid-wide generation barrier between steps.
// ---------------------------------------------------------------------------
__global__ void __launch_bounds__(128, 1) rnn_kernel(
    const float* __restrict__ Wh, const float* __restrict__ bh,
    float* __restrict__ out)
{
    float* hfinal = out;
    float* hall = out + (size_t)BB * HH;

    __shared__ float Hs[2][64][36];
    __shared__ float Ws[2][32][36];
    __shared__ unsigned sbase;

    const int tid = threadIdx.x;
    const int bidx = blockIdx.x;
    const int jt = bidx & 31;
    const int bt = bidx >> 5;
    const int b0 = bt * 64;
    const int j0 = jt * 32;

    const int tjj = tid & 7;     // j group
    const int tbq = tid >> 3;    // 0..15, b rows tbq*4 + r

    if (tid == 0) sbase = *(volatile unsigned*)&g_gen;
    __syncthreads();
    const unsigned base = sbase;

    // zero h buffer 0 (the t=0 input state) — replay-safe
    {
        float4 z = make_float4(0.f, 0.f, 0.f, 0.f);
        for (int i = bidx * 128 + tid; i < BB * HH / 4; i += NB2 * 128)
            ((float4*)g_h)[i] = z;
    }
    unsigned gen = 1;
    grid_sync(base, gen++, NB2);

    float bhv[4];
#pragma unroll
    for (int q = 0; q < 4; ++q) bhv[q] = bh[j0 + tjj + 8 * q];

    const int lr = tid >> 3;     // loader row 0..15
    const int ls = tid & 7;      // loader seg

    const float* Wb = Wh + (size_t)j0 * HH;

    for (int t = 0; t < TT; ++t) {
        const float* hr = g_h + (size_t)(t & 1) * (BB * HH);
        float* hw = g_h + (size_t)((t & 1) ^ 1) * (BB * HH);

        float acc[4][4];
#pragma unroll
        for (int r = 0; r < 4; ++r)
#pragma unroll
            for (int q = 0; q < 4; ++q) acc[r][q] = 0.0f;

        float4 ha0, ha1, ha2, ha3, wa0, wa1;
        {
            const float* ph = hr + (size_t)(b0 + lr) * HH + ls * 4;
            ha0 = *(const float4*)ph;
            ha1 = *(const float4*)(ph + (size_t)16 * HH);
            ha2 = *(const float4*)(ph + (size_t)32 * HH);
            ha3 = *(const float4*)(ph + (size_t)48 * HH);
            const float* pw = Wb + (size_t)lr * HH + ls * 4;
            wa0 = *(const float4*)pw;
            wa1 = *(const float4*)(pw + (size_t)16 * HH);
        }

#pragma unroll 1
        for (int c = 0; c < KK / 32; ++c) {
            const int buf = c & 1;
            *(float4*)&Hs[buf][lr][ls * 4]      = ha0;
            *(float4*)&Hs[buf][lr + 16][ls * 4] = ha1;
            *(float4*)&Hs[buf][lr + 32][ls * 4] = ha2;
            *(float4*)&Hs[buf][lr + 48][ls * 4] = ha3;
            *(float4*)&Ws[buf][lr][ls * 4]      = wa0;
            *(float4*)&Ws[buf][lr + 16][ls * 4] = wa1;
            __syncthreads();

            if (c + 1 < KK / 32) {
                const int kn = (c + 1) * 32;
                const float* ph = hr + (size_t)(b0 + lr) * HH + kn + ls * 4;
                ha0 = *(const float4*)ph;
                ha1 = *(const float4*)(ph + (size_t)16 * HH);
                ha2 = *(const float4*)(ph + (size_t)32 * HH);
                ha3 = *(const float4*)(ph + (size_t)48 * HH);
                const float* pw = Wb + (size_t)lr * HH + kn + ls * 4;
                wa0 = *(const float4*)pw;
                wa1 = *(const float4*)(pw + (size_t)16 * HH);
            }

#pragma unroll
            for (int kk = 0; kk < 8; ++kk) {
                float4 a[4], w[4];
#pragma unroll
                for (int r = 0; r < 4; ++r)
                    a[r] = *(const float4*)&Hs[buf][tbq * 4 + r][kk * 4];
#pragma unroll
                for (int q = 0; q < 4; ++q)
                    w[q] = *(const float4*)&Ws[buf][tjj + 8 * q][kk * 4];
#pragma unroll
                for (int r = 0; r < 4; ++r)
#pragma unroll
                    for (int q = 0; q < 4; ++q) {
                        acc[r][q] = fmaf(a[r].x, w[q].x, acc[r][q]);
                        acc[r][q] = fmaf(a[r].y, w[q].y, acc[r][q]);
                        acc[r][q] = fmaf(a[r].z, w[q].z, acc[r][q]);
                        acc[r][q] = fmaf(a[r].w, w[q].w, acc[r][q]);
                    }
            }
        }

        // epilogue: h = tanh(acc + bh + xp); xp lives in hall[t] and is
        // overwritten in-place (same thread reads then writes each element).
        float* hat = hall + (size_t)t * BB * HH;
#pragma unroll
        for (int r = 0; r < 4; ++r) {
            const int b = b0 + tbq * 4 + r;
#pragma unroll
            for (int q = 0; q < 4; ++q) {
                const int j = j0 + tjj + 8 * q;
                const size_t idx = (size_t)b * HH + j;
                const float v = tanh_fast(acc[r][q] + bhv[q] + hat[idx]);
                hw[idx] = v;
                hat[idx] = v;
                if (t == TT - 1) hfinal[idx] = v;
            }
        }

        grid_sync(base, gen++, NB2);
    }
}

extern "C" void kernel_launch(void* const* d_in, const int* in_sizes, int n_in,
                              void* d_out, int out_size)
{
    (void)in_sizes; (void)n_in; (void)out_size;
    const float* x  = (const float*)d_in[0];
    const float* Wx = (const float*)d_in[1];
    const float* bx = (const float*)d_in[2];
    const float* Wh = (const float*)d_in[3];
    const float* bh = (const float*)d_in[4];
    float* out = (float*)d_out;
    float* xp = out + (size_t)BB * HH;   // h_all region doubles as xp scratch

    dim3 g1(HH / 64, (TT * BB) / 64);
    xproj_kernel<<<g1, 256>>>(x, Wx, bx, xp);
    rnn_kernel<<<NB2, 128>>>(Wh, bh, out);
}

// round 3
// speedup vs baseline: 2.0792x; 2.0792x over previous
#include <cuda_runtime.h>
#include <cuda_bf16.h>
#include <cstdint>

#define TT 512
#define BB 256
#define HH 1024
#define KK 1024

// ---------------- device globals (static scratch; no allocations) ----------
__device__ __align__(16) unsigned short g_hhi[2][BB*HH];
__device__ __align__(16) unsigned short g_hlo[2][BB*HH];
__device__ unsigned g_count;
__device__ unsigned g_gen;

// ---------------- helpers ---------------------------------------------------
__device__ __forceinline__ uint32_t smem_u32(const void* p) {
    uint32_t a;
    asm("{ .reg .u64 t; cvta.to.shared.u64 t, %1; cvt.u32.u64 %0, t; }"
        : "=r"(a) : "l"(p));
    return a;
}

__device__ __forceinline__ void ldsm4(uint32_t* r, uint32_t addr) {
    asm volatile("ldmatrix.sync.aligned.m8n8.x4.shared.b16 {%0,%1,%2,%3}, [%4];"
        : "=r"(r[0]), "=r"(r[1]), "=r"(r[2]), "=r"(r[3]) : "r"(addr));
}

__device__ __forceinline__ void mma16816(float* c, const uint32_t* a, const uint32_t* b) {
    asm volatile("mma.sync.aligned.m16n8k16.row.col.f32.bf16.bf16.f32 "
        "{%0,%1,%2,%3}, {%4,%5,%6,%7}, {%8,%9}, {%0,%1,%2,%3};"
        : "+f"(c[0]), "+f"(c[1]), "+f"(c[2]), "+f"(c[3])
        : "r"(a[0]), "r"(a[1]), "r"(a[2]), "r"(a[3]), "r"(b[0]), "r"(b[1]));
}

#define CP16(dst, src) \
    asm volatile("{\n\t.reg .u64 g;\n\tcvta.to.global.u64 g, %1;\n\t" \
                 "cp.async.cg.shared.global [%0], [g], 16;\n\t}" \
                 :: "r"(dst), "l"(src) : "memory")
#define CP_COMMIT() asm volatile("cp.async.commit_group;" ::: "memory")
#define CP_WAIT0()  asm volatile("cp.async.wait_group 0;" ::: "memory")
#define CP_WAIT1()  asm volatile("cp.async.wait_group 1;" ::: "memory")

__device__ __forceinline__ float tanh_fast(float x) {
    float e = __expf(2.0f * x);
    return 1.0f - 2.0f / (e + 1.0f);
}

// pack 2 consecutive fp32 into bf16x2 hi and lo (residual) words
__device__ __forceinline__ void split2(float a, float b, uint32_t& hi, uint32_t& lo) {
    __nv_bfloat16 ha = __float2bfloat16_rn(a);
    __nv_bfloat16 hb = __float2bfloat16_rn(b);
    float ra = a - __bfloat162float(ha);
    float rb = b - __bfloat162float(hb);
    __nv_bfloat16 la = __float2bfloat16_rn(ra);
    __nv_bfloat16 lb = __float2bfloat16_rn(rb);
    hi = (uint32_t)__bfloat16_as_ushort(ha) | ((uint32_t)__bfloat16_as_ushort(hb) << 16);
    lo = (uint32_t)__bfloat16_as_ushort(la) | ((uint32_t)__bfloat16_as_ushort(lb) << 16);
}

__device__ __forceinline__ void grid_sync(unsigned base, unsigned gen, unsigned nb) {
    __syncthreads();
    if (threadIdx.x == 0) {
        const unsigned target = base + gen;
        __threadfence();
        unsigned a = atomicAdd(&g_count, 1u);
        if (a == nb - 1u) {
            g_count = 0u;
            __threadfence();
            atomicExch(&g_gen, target);
        } else {
            while ((int)(*(volatile unsigned*)&g_gen - target) < 0) __nanosleep(64);
        }
        __threadfence();
    }
    __syncthreads();
}

// ---------------------------------------------------------------------------
// Phase 1: XP = x @ Wx^T + bx.  HMMA split-bf16 (3 terms).
// grid (8, 1024), block 256 (8 warps). Block tile 128m x 128n, warp 64m x 32n.
// K chunk = 32, single smem buffer, register-staged fp32 prefetch.
// smem rows padded to 80B (32 bf16 + 16B pad): conflict-free ldmatrix.
// ---------------------------------------------------------------------------
#define P1_AH 0
#define P1_AL 10240
#define P1_BH 20480
#define P1_BL 30720
#define P1_SMEM 40960

__global__ void __launch_bounds__(256, 1)
xproj_hmma(const float* __restrict__ X, const float* __restrict__ Wx,
           const float* __restrict__ bx, float* __restrict__ XP)
{
    extern __shared__ char smem[];
    __shared__ float bxs[128];
    const uint32_t sb = smem_u32(smem);
    const int tid = threadIdx.x;
    const int lane = tid & 31;
    const int w = tid >> 5;
    const int wm = w >> 2;           // 0..1  (64 m rows)
    const int wn = w & 3;            // 0..3  (32 n cols)
    const int n0 = blockIdx.x * 128;
    const int m0 = blockIdx.y * 128;

    if (tid < 128) bxs[tid] = bx[n0 + tid];

    // per-lane ldmatrix relative addresses
    const uint32_t aRel = (uint32_t)((wm * 64 + (lane & 15)) * 80 + (lane >> 4) * 16);
    const uint32_t bRel = (uint32_t)((wn * 32 + ((lane >> 4) & 1) * 8 + (lane & 7)) * 80
                                     + ((lane >> 3) & 1) * 16);

    float cc[4][4][4];
#pragma unroll
    for (int a = 0; a < 4; ++a)
#pragma unroll
        for (int b = 0; b < 4; ++b)
#pragma unroll
            for (int q = 0; q < 4; ++q) cc[a][b][q] = 0.0f;

    float4 va[4], vb[4];
    // prefetch chunk 0
#pragma unroll
    for (int i = 0; i < 4; ++i) {
        int u = tid + 256 * i;
        int row = u >> 3, k4 = u & 7;
        va[i] = *(const float4*)(X + (size_t)(m0 + row) * KK + k4 * 4);
        vb[i] = *(const float4*)(Wx + (size_t)(n0 + row) * KK + k4 * 4);
    }

#pragma unroll 1
    for (int c = 0; c < 32; ++c) {
        // store staged regs (split to bf16 hi/lo)
#pragma unroll
        for (int i = 0; i < 4; ++i) {
            int u = tid + 256 * i;
            int row = u >> 3, k4 = u & 7;
            uint2 hi, lo;
            split2(va[i].x, va[i].y, hi.x, lo.x);
            split2(va[i].z, va[i].w, hi.y, lo.y);
            uint32_t off = (uint32_t)(row * 80 + k4 * 8);
            *(uint2*)(smem + P1_AH + off) = hi;
            *(uint2*)(smem + P1_AL + off) = lo;
            split2(vb[i].x, vb[i].y, hi.x, lo.x);
            split2(vb[i].z, vb[i].w, hi.y, lo.y);
            *(uint2*)(smem + P1_BH + off) = hi;
            *(uint2*)(smem + P1_BL + off) = lo;
        }
        __syncthreads();

        if (c < 31) {
            const int k0 = (c + 1) * 32;
#pragma unroll
            for (int i = 0; i < 4; ++i) {
                int u = tid + 256 * i;
                int row = u >> 3, k4 = u & 7;
                va[i] = *(const float4*)(X + (size_t)(m0 + row) * KK + k0 + k4 * 4);
                vb[i] = *(const float4*)(Wx + (size_t)(n0 + row) * KK + k0 + k4 * 4);
            }
        }

#pragma unroll
        for (int kk = 0; kk < 2; ++kk) {
            const uint32_t ka = kk * 32;
            uint32_t ah[4][4], al[4][4], bh[8], bl[8];
#pragma unroll
            for (int mi = 0; mi < 4; ++mi) {
                ldsm4(ah[mi], sb + P1_AH + aRel + mi * 1280 + ka);
                ldsm4(al[mi], sb + P1_AL + aRel + mi * 1280 + ka);
            }
            ldsm4(bh,     sb + P1_BH + bRel + ka);
            ldsm4(bh + 4, sb + P1_BH + bRel + 1280 + ka);
            ldsm4(bl,     sb + P1_BL + bRel + ka);
            ldsm4(bl + 4, sb + P1_BL + bRel + 1280 + ka);
#pragma unroll
            for (int mi = 0; mi < 4; ++mi)
#pragma unroll
                for (int ni = 0; ni < 4; ++ni) {
                    mma16816(cc[mi][ni], ah[mi], bh + 2 * ni);
                    mma16816(cc[mi][ni], ah[mi], bl + 2 * ni);
                    mma16816(cc[mi][ni], al[mi], bh + 2 * ni);
                }
        }
        __syncthreads();
    }

    // epilogue: add bias, write fp32
#pragma unroll
    for (int mi = 0; mi < 4; ++mi)
#pragma unroll
        for (int ni = 0; ni < 4; ++ni)
#pragma unroll
            for (int p = 0; p < 2; ++p) {
                int row = wm * 64 + mi * 16 + (lane >> 2) + p * 8;
                int col = wn * 32 + ni * 8 + (lane & 3) * 2;
                float2 v;
                v.x = cc[mi][ni][2 * p]     + bxs[col];
                v.y = cc[mi][ni][2 * p + 1] + bxs[col + 1];
                *(float2*)(XP + (size_t)(m0 + row) * HH + n0 + col) = v;
            }
}

// ---------------------------------------------------------------------------
// Phase 2: persistent RNN scan. 128 blocks = 4 m-tiles(64) x 32 n-tiles(32).
// 128 threads (4 warps, warp tile 32m x 16n). Wh hi/lo resident in smem
// (rows padded to 2064B). h-state streamed as bf16 hi/lo via cp.async,
// double-buffered K chunks of 64. One grid barrier per timestep.
// ---------------------------------------------------------------------------
#define P2_NBLK 128
#define P2_BH   0
#define P2_BL   66048
#define P2_AB   132096           // A bufs: buf*18432 + split*9216
#define P2_SMEM 168960

__global__ void __launch_bounds__(128, 1)
rnn_hmma(const float* __restrict__ Wh, const float* __restrict__ bh,
         float* __restrict__ out)
{
    extern __shared__ char smem[];
    __shared__ float bhs[32];
    __shared__ unsigned sbase;
    const uint32_t sb = smem_u32(smem);
    const int tid = threadIdx.x;
    const int lane = tid & 31;
    const int w = tid >> 5;
    const int wm = w >> 1;           // 0..1 (32 m rows)
    const int wn = w & 1;            // 0..1 (16 n cols)
    const int bidx = blockIdx.x;
    const int jt = bidx & 31, bt = bidx >> 5;
    const int j0 = jt * 32, b0 = bt * 64;

    float* hfinal = out;
    float* hall = out + (size_t)BB * HH;

    if (tid == 0) sbase = *(volatile unsigned*)&g_gen;
    if (tid < 32) bhs[tid] = bh[j0 + tid];

    // load + split resident Wh tile: 32 rows x 1024 k
#pragma unroll 1
    for (int i = tid; i < 32 * 256; i += 128) {
        int row = i >> 8, k4 = i & 255;
        float4 v = *(const float4*)(Wh + (size_t)(j0 + row) * KK + k4 * 4);
        uint2 hi, lo;
        split2(v.x, v.y, hi.x, lo.x);
        split2(v.z, v.w, hi.y, lo.y);
        uint32_t off = (uint32_t)(row * 2064 + k4 * 8);
        *(uint2*)(smem + P2_BH + off) = hi;
        *(uint2*)(smem + P2_BL + off) = lo;
    }

    // zero the t=0 hidden-state splits (replay-safe)
    {
        uint4 z = make_uint4(0, 0, 0, 0);
        for (int i = bidx * 128 + tid; i < BB * HH / 8; i += P2_NBLK * 128) {
            ((uint4*)g_hhi[0])[i] = z;
            ((uint4*)g_hlo[0])[i] = z;
        }
    }
    __syncthreads();
    const unsigned base = sbase;
    unsigned gen = 1;
    grid_sync(base, gen++, P2_NBLK);

    // per-lane ldmatrix relative addresses
    const uint32_t aRel = (uint32_t)((wm * 32 + (lane & 15)) * 144 + (lane >> 4) * 16);
    const uint32_t bRel = (uint32_t)((wn * 16 + ((lane >> 4) & 1) * 8 + (lane & 7)) * 2064
                                     + ((lane >> 3) & 1) * 16);
    // per-lane cp.async coords
    const int cprow0 = tid >> 3, cpseg = tid & 7;

#pragma unroll 1
    for (int t = 0; t < TT; ++t) {
        const unsigned short* hrh = g_hhi[t & 1];
        const unsigned short* hrl = g_hlo[t & 1];
        unsigned short* hwh = g_hhi[(t & 1) ^ 1];
        unsigned short* hwl = g_hlo[(t & 1) ^ 1];

        float cc[2][2][4];
#pragma unroll
        for (int a = 0; a < 2; ++a)
#pragma unroll
            for (int b = 0; b < 2; ++b)
#pragma unroll
                for (int q = 0; q < 4; ++q) cc[a][b][q] = 0.0f;

        // issue chunk 0
#pragma unroll
        for (int i = 0; i < 4; ++i) {
            int row = cprow0 + 16 * i;
            uint32_t dst = sb + P2_AB + (uint32_t)(row * 144 + cpseg * 16);
            size_t src = (size_t)(b0 + row) * KK + cpseg * 8;
            CP16(dst, hrh + src);
            CP16(dst + 9216, hrl + src);
        }
        CP_COMMIT();

#pragma unroll 1
        for (int c = 0; c < 16; ++c) {
            const int buf = c & 1;
            if (c + 1 < 16) {
                const int nb = (c + 1) & 1;
#pragma unroll
                for (int i = 0; i < 4; ++i) {
                    int row = cprow0 + 16 * i;
                    uint32_t dst = sb + P2_AB + (uint32_t)(nb * 18432 + row * 144 + cpseg * 16);
                    size_t src = (size_t)(b0 + row) * KK + (c + 1) * 64 + cpseg * 8;
                    CP16(dst, hrh + src);
                    CP16(dst + 9216, hrl + src);
                }
                CP_COMMIT();
                CP_WAIT1();
            } else {
                CP_WAIT0();
            }
            __syncthreads();

            const uint32_t aH = sb + P2_AB + (uint32_t)(buf * 18432) + aRel;
            const uint32_t aL = aH + 9216;
            const uint32_t kbase = (uint32_t)(c * 64) * 2;
#pragma unroll
            for (int kk = 0; kk < 4; ++kk) {
                const uint32_t ka = kk * 32;
                uint32_t ah0[4], ah1[4], al0[4], al1[4], bhf[4], blf[4];
                ldsm4(ah0, aH + ka);
                ldsm4(ah1, aH + ka + 2304);
                ldsm4(al0, aL + ka);
                ldsm4(al1, aL + ka + 2304);
                ldsm4(bhf, sb + P2_BH + bRel + kbase + ka);
                ldsm4(blf, sb + P2_BL + bRel + kbase + ka);
#pragma unroll
                for (int ni = 0; ni < 2; ++ni) {
                    mma16816(cc[0][ni], ah0, bhf + 2 * ni);
                    mma16816(cc[0][ni], ah0, blf + 2 * ni);
                    mma16816(cc[0][ni], al0, bhf + 2 * ni);
                    mma16816(cc[1][ni], ah1, bhf + 2 * ni);
                    mma16816(cc[1][ni], ah1, blf + 2 * ni);
                    mma16816(cc[1][ni], al1, bhf + 2 * ni);
                }
            }
            __syncthreads();
        }

        // epilogue: v = tanh(gemm + bh + xp); overwrite xp (hall[t]) with v,
        // write bf16 hi/lo h-state, and hfinal at the last step.
        float* hat = hall + (size_t)t * (BB * HH);
#pragma unroll
        for (int mi = 0; mi < 2; ++mi)
#pragma unroll
            for (int ni = 0; ni < 2; ++ni)
#pragma unroll
                for (int p = 0; p < 2; ++p) {
                    int row = wm * 32 + mi * 16 + (lane >> 2) + p * 8;
                    int col = wn * 16 + ni * 8 + (lane & 3) * 2;
                    size_t idx = (size_t)(b0 + row) * HH + j0 + col;
                    float2 xp = *(float2*)(hat + idx);
                    float v0 = tanh_fast(cc[mi][ni][2 * p]     + bhs[col]     + xp.x);
                    float v1 = tanh_fast(cc[mi][ni][2 * p + 1] + bhs[col + 1] + xp.y);
                    *(float2*)(hat + idx) = make_float2(v0, v1);
                    if (t == TT - 1) *(float2*)(hfinal + idx) = make_float2(v0, v1);
                    uint32_t hi, lo;
                    split2(v0, v1, hi, lo);
                    *(uint32_t*)(hwh + idx) = hi;
                    *(uint32_t*)(hwl + idx) = lo;
                }

        grid_sync(base, gen++, P2_NBLK);
    }
}

// ---------------------------------------------------------------------------
extern "C" void kernel_launch(void* const* d_in, const int* in_sizes, int n_in,
                              void* d_out, int out_size)
{
    (void)in_sizes; (void)n_in; (void)out_size;
    const float* x  = (const float*)d_in[0];
    const float* Wx = (const float*)d_in[1];
    const float* bx = (const float*)d_in[2];
    const float* Wh = (const float*)d_in[3];
    const float* bh = (const float*)d_in[4];
    float* out = (float*)d_out;
    float* xp = out + (size_t)BB * HH;   // h_all region doubles as xp scratch

    cudaFuncSetAttribute(xproj_hmma, cudaFuncAttributeMaxDynamicSharedMemorySize, P1_SMEM);
    cudaFuncSetAttribute(rnn_hmma,  cudaFuncAttributeMaxDynamicSharedMemorySize, P2_SMEM);

    dim3 g1(HH / 128, (TT * BB) / 128);
    xproj_hmma<<<g1, 256, P1_SMEM>>>(x, Wx, bx, xp);
    rnn_hmma<<<P2_NBLK, 128, P2_SMEM>>>(Wh, bh, out);
}

// round 4
// speedup vs baseline: 2.7237x; 1.3100x over previous
#include <cuda_runtime.h>
#include <cuda_bf16.h>
#include <cstdint>

#define TT 512
#define BB 256
#define HH 1024
#define KK 1024

// ---------------- device globals (static scratch; no allocations) ----------
__device__ __align__(16) unsigned short g_hhi[2][BB*HH];
__device__ __align__(16) unsigned short g_hlo[2][BB*HH];
__device__ unsigned g_count;
__device__ unsigned g_gen;

// ---------------- helpers ---------------------------------------------------
__device__ __forceinline__ uint32_t smem_u32(const void* p) {
    uint32_t a;
    asm("{ .reg .u64 t; cvta.to.shared.u64 t, %1; cvt.u32.u64 %0, t; }"
        : "=r"(a) : "l"(p));
    return a;
}

__device__ __forceinline__ void ldsm4(uint32_t* r, uint32_t addr) {
    asm volatile("ldmatrix.sync.aligned.m8n8.x4.shared.b16 {%0,%1,%2,%3}, [%4];"
        : "=r"(r[0]), "=r"(r[1]), "=r"(r[2]), "=r"(r[3]) : "r"(addr));
}

__device__ __forceinline__ void mma16816(float* c, const uint32_t* a, const uint32_t* b) {
    asm volatile("mma.sync.aligned.m16n8k16.row.col.f32.bf16.bf16.f32 "
        "{%0,%1,%2,%3}, {%4,%5,%6,%7}, {%8,%9}, {%0,%1,%2,%3};"
        : "+f"(c[0]), "+f"(c[1]), "+f"(c[2]), "+f"(c[3])
        : "r"(a[0]), "r"(a[1]), "r"(a[2]), "r"(a[3]), "r"(b[0]), "r"(b[1]));
}

#define CP16(dst, src) \
    asm volatile("{\n\t.reg .u64 g;\n\tcvta.to.global.u64 g, %1;\n\t" \
                 "cp.async.cg.shared.global [%0], [g], 16;\n\t}" \
                 :: "r"(dst), "l"(src) : "memory")
#define CP_COMMIT() asm volatile("cp.async.commit_group;" ::: "memory")
#define CP_WAITN(n) asm volatile("cp.async.wait_group %0;" :: "n"(n) : "memory")

#define GROUP_BAR(id) asm volatile("bar.sync %0, %1;" :: "r"(id), "r"(128) : "memory")

__device__ __forceinline__ float tanh_fast(float x) {
    float e = __expf(2.0f * x);
    return 1.0f - 2.0f / (e + 1.0f);
}

// pack 2 consecutive fp32 into bf16x2 hi and lo (residual) words
__device__ __forceinline__ void split2(float a, float b, uint32_t& hi, uint32_t& lo) {
    __nv_bfloat16 ha = __float2bfloat16_rn(a);
    __nv_bfloat16 hb = __float2bfloat16_rn(b);
    float ra = a - __bfloat162float(ha);
    float rb = b - __bfloat162float(hb);
    __nv_bfloat16 la = __float2bfloat16_rn(ra);
    __nv_bfloat16 lb = __float2bfloat16_rn(rb);
    hi = (uint32_t)__bfloat16_as_ushort(ha) | ((uint32_t)__bfloat16_as_ushort(hb) << 16);
    lo = (uint32_t)__bfloat16_as_ushort(la) | ((uint32_t)__bfloat16_as_ushort(lb) << 16);
}

__device__ __forceinline__ void grid_sync(unsigned base, unsigned gen, unsigned nb) {
    __syncthreads();
    if (threadIdx.x == 0) {
        const unsigned target = base + gen;
        __threadfence();
        unsigned a = atomicAdd(&g_count, 1u);
        if (a == nb - 1u) {
            g_count = 0u;
            __threadfence();
            atomicExch(&g_gen, target);
        } else {
            while ((int)(*(volatile unsigned*)&g_gen - target) < 0) __nanosleep(64);
        }
        __threadfence();
    }
    __syncthreads();
}

// ---------------------------------------------------------------------------
// Phase 1 (UNCHANGED from R3 — measured at its quarter-rate MMA floor).
// ---------------------------------------------------------------------------
#define P1_AH 0
#define P1_AL 10240
#define P1_BH 20480
#define P1_BL 30720
#define P1_SMEM 40960

__global__ void __launch_bounds__(256, 1)
xproj_hmma(const float* __restrict__ X, const float* __restrict__ Wx,
           const float* __restrict__ bx, float* __restrict__ XP)
{
    extern __shared__ char smem[];
    __shared__ float bxs[128];
    const uint32_t sb = smem_u32(smem);
    const int tid = threadIdx.x;
    const int lane = tid & 31;
    const int w = tid >> 5;
    const int wm = w >> 2;
    const int wn = w & 3;
    const int n0 = blockIdx.x * 128;
    const int m0 = blockIdx.y * 128;

    if (tid < 128) bxs[tid] = bx[n0 + tid];

    const uint32_t aRel = (uint32_t)((wm * 64 + (lane & 15)) * 80 + (lane >> 4) * 16);
    const uint32_t bRel = (uint32_t)((wn * 32 + ((lane >> 4) & 1) * 8 + (lane & 7)) * 80
                                     + ((lane >> 3) & 1) * 16);

    float cc[4][4][4];
#pragma unroll
    for (int a = 0; a < 4; ++a)
#pragma unroll
        for (int b = 0; b < 4; ++b)
#pragma unroll
            for (int q = 0; q < 4; ++q) cc[a][b][q] = 0.0f;

    float4 va[4], vb[4];
#pragma unroll
    for (int i = 0; i < 4; ++i) {
        int u = tid + 256 * i;
        int row = u >> 3, k4 = u & 7;
        va[i] = *(const float4*)(X + (size_t)(m0 + row) * KK + k4 * 4);
        vb[i] = *(const float4*)(Wx + (size_t)(n0 + row) * KK + k4 * 4);
    }

#pragma unroll 1
    for (int c = 0; c < 32; ++c) {
#pragma unroll
        for (int i = 0; i < 4; ++i) {
            int u = tid + 256 * i;
            int row = u >> 3, k4 = u & 7;
            uint2 hi, lo;
            split2(va[i].x, va[i].y, hi.x, lo.x);
            split2(va[i].z, va[i].w, hi.y, lo.y);
            uint32_t off = (uint32_t)(row * 80 + k4 * 8);
            *(uint2*)(smem + P1_AH + off) = hi;
            *(uint2*)(smem + P1_AL + off) = lo;
            split2(vb[i].x, vb[i].y, hi.x, lo.x);
            split2(vb[i].z, vb[i].w, hi.y, lo.y);
            *(uint2*)(smem + P1_BH + off) = hi;
            *(uint2*)(smem + P1_BL + off) = lo;
        }
        __syncthreads();

        if (c < 31) {
            const int k0 = (c + 1) * 32;
#pragma unroll
            for (int i = 0; i < 4; ++i) {
                int u = tid + 256 * i;
                int row = u >> 3, k4 = u & 7;
                va[i] = *(const float4*)(X + (size_t)(m0 + row) * KK + k0 + k4 * 4);
                vb[i] = *(const float4*)(Wx + (size_t)(n0 + row) * KK + k0 + k4 * 4);
            }
        }

#pragma unroll
        for (int kk = 0; kk < 2; ++kk) {
            const uint32_t ka = kk * 32;
            uint32_t ah[4][4], al[4][4], bh[8], bl[8];
#pragma unroll
            for (int mi = 0; mi < 4; ++mi) {
                ldsm4(ah[mi], sb + P1_AH + aRel + mi * 1280 + ka);
                ldsm4(al[mi], sb + P1_AL + aRel + mi * 1280 + ka);
            }
            ldsm4(bh,     sb + P1_BH + bRel + ka);
            ldsm4(bh + 4, sb + P1_BH + bRel + 1280 + ka);
            ldsm4(bl,     sb + P1_BL + bRel + ka);
            ldsm4(bl + 4, sb + P1_BL + bRel + 1280 + ka);
#pragma unroll
            for (int mi = 0; mi < 4; ++mi)
#pragma unroll
                for (int ni = 0; ni < 4; ++ni) {
                    mma16816(cc[mi][ni], ah[mi], bh + 2 * ni);
                    mma16816(cc[mi][ni], ah[mi], bl + 2 * ni);
                    mma16816(cc[mi][ni], al[mi], bh + 2 * ni);
                }
        }
        __syncthreads();
    }

#pragma unroll
    for (int mi = 0; mi < 4; ++mi)
#pragma unroll
        for (int ni = 0; ni < 4; ++ni)
#pragma unroll
            for (int p = 0; p < 2; ++p) {
                int row = wm * 64 + mi * 16 + (lane >> 2) + p * 8;
                int col = wn * 32 + ni * 8 + (lane & 3) * 2;
                float2 v;
                v.x = cc[mi][ni][2 * p]     + bxs[col];
                v.y = cc[mi][ni][2 * p + 1] + bxs[col + 1];
                *(float2*)(XP + (size_t)(m0 + row) * HH + n0 + col) = v;
            }
}

// ---------------------------------------------------------------------------
// Phase 2 v2: persistent RNN. 128 blocks = 4 m-tiles(64) x 32 n-tiles(32),
// 256 threads = 2 k-groups x 4 warps (warp tile 32m x 16n). Wh resident.
// Per group: 8 chunks of k64, 3-stage cp.async A stream, 1 named barrier
// per chunk. xp prefetched into registers at step start. Partial sums of
// group 1 combined via smem.
// ---------------------------------------------------------------------------
#define P2_NBLK 128
#define P2_WH_H 0
#define P2_WH_L 66048
#define P2_A    132096            // + kg*49152 + buf*16384 (+8192 for lo)
#define P2_SMEM 230400

__global__ void __launch_bounds__(256, 1)
rnn_hmma(const float* __restrict__ Wh, const float* __restrict__ bh,
         float* __restrict__ out)
{
    extern __shared__ char smem[];
    __shared__ float bhs[32];
    __shared__ unsigned sbase;
    const uint32_t sb = smem_u32(smem);
    const int tid = threadIdx.x;
    const int lane = tid & 31;
    const int w = tid >> 5;
    const int kg = w >> 2;           // k-group: 0 -> k[0,512), 1 -> k[512,1024)
    const int wl = w & 3;
    const int wm = wl >> 1;          // 0..1 (32 m rows)
    const int wn = wl & 1;           // 0..1 (16 n cols)
    const int tig = tid & 127;       // thread id within group
    const int bidx = blockIdx.x;
    const int jt = bidx & 31, bt = bidx >> 5;
    const int j0 = jt * 32, b0 = bt * 64;

    float* hfinal = out;
    float* hall = out + (size_t)BB * HH;

    if (tid == 0) sbase = *(volatile unsigned*)&g_gen;
    if (tid < 32) bhs[tid] = bh[j0 + tid];

    // load + split resident Wh tile: 32 rows x 1024 k (rows padded to 2064B)
#pragma unroll 1
    for (int i = tid; i < 32 * 256; i += 256) {
        int row = i >> 8, k4 = i & 255;
        float4 v = *(const float4*)(Wh + (size_t)(j0 + row) * KK + k4 * 4);
        uint2 hi, lo;
        split2(v.x, v.y, hi.x, lo.x);
        split2(v.z, v.w, hi.y, lo.y);
        uint32_t off = (uint32_t)(row * 2064 + k4 * 8);
        *(uint2*)(smem + P2_WH_H + off) = hi;
        *(uint2*)(smem + P2_WH_L + off) = lo;
    }

    // zero the t=0 hidden-state splits (replay-safe)
    {
        uint4 z = make_uint4(0, 0, 0, 0);
        for (int i = bidx * 256 + tid; i < BB * HH / 8; i += P2_NBLK * 256) {
            ((uint4*)g_hhi[0])[i] = z;
            ((uint4*)g_hlo[0])[i] = z;
        }
    }
    __syncthreads();
    const unsigned base = sbase;
    unsigned gen = 1;
    grid_sync(base, gen++, P2_NBLK);

    // ldmatrix A addressing (swizzled 128B rows)
    const uint32_t aLin = (uint32_t)((wm * 32 + (lane & 15)) * 128 + (lane >> 4) * 16);
    const uint32_t aXor = (uint32_t)((lane & 7) << 4);
    // ldmatrix B addressing (2064B padded rows)
    const uint32_t bRel = (uint32_t)((wn * 16 + ((lane >> 4) & 1) * 8 + (lane & 7)) * 2064
                                     + ((lane >> 3) & 1) * 16);
    const uint32_t kgOff = (uint32_t)(kg * 1024);   // byte offset into Wh rows
    // cp.async coords: 4 (row,seg) pairs per thread per split
    const int cprow0 = tig >> 3, cpseg = tig & 7;
    const uint32_t aBase = sb + P2_A + (uint32_t)(kg * 49152);
    const size_t kSrc0 = (size_t)kg * 512 + cpseg * 8;

    // epilogue/partial fragment coordinates
    int erow[2][2], ecol[2][2];
#pragma unroll
    for (int mi = 0; mi < 2; ++mi)
#pragma unroll
        for (int p = 0; p < 2; ++p)
            erow[mi][p] = wm * 32 + mi * 16 + (lane >> 2) + p * 8;
#pragma unroll
    for (int ni = 0; ni < 2; ++ni)
        ecol[ni][0] = wn * 16 + ni * 8 + (lane & 3) * 2;
    float* psm = (float*)(smem + P2_A + 49152);   // partial exchange (group1 buf0)

#pragma unroll 1
    for (int t = 0; t < TT; ++t) {
        const unsigned short* hrh = g_hhi[t & 1];
        const unsigned short* hrl = g_hlo[t & 1];
        unsigned short* hwh = g_hhi[(t & 1) ^ 1];
        unsigned short* hwl = g_hlo[(t & 1) ^ 1];
        float* hat = hall + (size_t)t * (BB * HH);

        // xp prefetch into registers (group 0 only; consumed in epilogue)
        float2 xpv[2][2][2];
        if (kg == 0) {
#pragma unroll
            for (int mi = 0; mi < 2; ++mi)
#pragma unroll
                for (int ni = 0; ni < 2; ++ni)
#pragma unroll
                    for (int p = 0; p < 2; ++p)
                        xpv[mi][ni][p] = *(const float2*)(hat +
                            (size_t)(b0 + erow[mi][p]) * HH + j0 + ecol[ni][0]);
        }

        float cc[2][2][4];
#pragma unroll
        for (int a = 0; a < 2; ++a)
#pragma unroll
            for (int b = 0; b < 2; ++b)
#pragma unroll
                for (int q = 0; q < 4; ++q) cc[a][b][q] = 0.0f;

        // prologue: issue chunks 0 and 1
#pragma unroll
        for (int pc = 0; pc < 2; ++pc) {
            const uint32_t bufb = aBase + (uint32_t)(pc * 16384);
#pragma unroll
            for (int i = 0; i < 4; ++i) {
                int row = cprow0 + 16 * i;
                uint32_t dst = bufb + (((uint32_t)(row * 128 + cpseg * 16)) ^ ((uint32_t)(row & 7) << 4));
                size_t src = (size_t)(b0 + row) * KK + kSrc0 + pc * 64;
                CP16(dst, hrh + src);
                CP16(dst + 8192, hrl + src);
            }
            CP_COMMIT();
        }

#pragma unroll 1
        for (int c = 0; c < 8; ++c) {
            if (c < 7) { CP_WAITN(1); } else { CP_WAITN(0); }
            GROUP_BAR(kg + 1);
            if (c + 2 < 8) {
                const uint32_t bufb = aBase + (uint32_t)(((c + 2) % 3) * 16384);
#pragma unroll
                for (int i = 0; i < 4; ++i) {
                    int row = cprow0 + 16 * i;
                    uint32_t dst = bufb + (((uint32_t)(row * 128 + cpseg * 16)) ^ ((uint32_t)(row & 7) << 4));
                    size_t src = (size_t)(b0 + row) * KK + kSrc0 + (c + 2) * 64;
                    CP16(dst, hrh + src);
                    CP16(dst + 8192, hrl + src);
                }
                CP_COMMIT();
            }

            const uint32_t aH = aBase + (uint32_t)((c % 3) * 16384);
            const uint32_t aL = aH + 8192;
            const uint32_t kOff = kgOff + (uint32_t)(c * 128);
#pragma unroll
            for (int kk = 0; kk < 4; ++kk) {
                const uint32_t ka = kk * 32;
                uint32_t ah0[4], ah1[4], al0[4], al1[4], bhf[4], blf[4];
                ldsm4(ah0, aH + ((aLin + ka) ^ aXor));
                ldsm4(ah1, aH + ((aLin + 2048 + ka) ^ aXor));
                ldsm4(al0, aL + ((aLin + ka) ^ aXor));
                ldsm4(al1, aL + ((aLin + 2048 + ka) ^ aXor));
                ldsm4(bhf, sb + P2_WH_H + bRel + kOff + ka);
                ldsm4(blf, sb + P2_WH_L + bRel + kOff + ka);
#pragma unroll
                for (int ni = 0; ni < 2; ++ni) {
                    mma16816(cc[0][ni], ah0, bhf + 2 * ni);
                    mma16816(cc[0][ni], ah0, blf + 2 * ni);
                    mma16816(cc[0][ni], al0, bhf + 2 * ni);
                    mma16816(cc[1][ni], ah1, bhf + 2 * ni);
                    mma16816(cc[1][ni], ah1, blf + 2 * ni);
                    mma16816(cc[1][ni], al1, bhf + 2 * ni);
                }
            }
        }

        // group 1 publishes partials
        if (kg == 1) {
#pragma unroll
            for (int mi = 0; mi < 2; ++mi)
#pragma unroll
                for (int ni = 0; ni < 2; ++ni)
#pragma unroll
                    for (int p = 0; p < 2; ++p)
                        *(float2*)&psm[erow[mi][p] * 32 + ecol[ni][0]] =
                            make_float2(cc[mi][ni][2 * p], cc[mi][ni][2 * p + 1]);
        }
        __syncthreads();

        // group 0 combines + epilogue
        if (kg == 0) {
#pragma unroll
            for (int mi = 0; mi < 2; ++mi)
#pragma unroll
                for (int ni = 0; ni < 2; ++ni)
#pragma unroll
                    for (int p = 0; p < 2; ++p) {
                        const int row = erow[mi][p], col = ecol[ni][0];
                        float2 pp = *(float2*)&psm[row * 32 + col];
                        size_t idx = (size_t)(b0 + row) * HH + j0 + col;
                        float v0 = tanh_fast(cc[mi][ni][2 * p]     + pp.x + bhs[col]     + xpv[mi][ni][p].x);
                        float v1 = tanh_fast(cc[mi][ni][2 * p + 1] + pp.y + bhs[col + 1] + xpv[mi][ni][p].y);
                        *(float2*)(hat + idx) = make_float2(v0, v1);
                        if (t == TT - 1) *(float2*)(hfinal + idx) = make_float2(v0, v1);
                        uint32_t hi, lo;
                        split2(v0, v1, hi, lo);
                        *(uint32_t*)(hwh + idx) = hi;
                        *(uint32_t*)(hwl + idx) = lo;
                    }
        }

        grid_sync(base, gen++, P2_NBLK);
    }
}

// ---------------------------------------------------------------------------
extern "C" void kernel_launch(void* const* d_in, const int* in_sizes, int n_in,
                              void* d_out, int out_size)
{
    (void)in_sizes; (void)n_in; (void)out_size;
    const float* x  = (const float*)d_in[0];
    const float* Wx = (const float*)d_in[1];
    const float* bx = (const float*)d_in[2];
    const float* Wh = (const float*)d_in[3];
    const float* bh = (const float*)d_in[4];
    float* out = (float*)d_out;
    float* xp = out + (size_t)BB * HH;   // h_all region doubles as xp scratch

    cudaFuncSetAttribute(xproj_hmma, cudaFuncAttributeMaxDynamicSharedMemorySize, P1_SMEM);
    cudaFuncSetAttribute(rnn_hmma,  cudaFuncAttributeMaxDynamicSharedMemorySize, P2_SMEM);

    dim3 g1(HH / 128, (TT * BB) / 128);
    xproj_hmma<<<g1, 256, P1_SMEM>>>(x, Wx, bx, xp);
    rnn_hmma<<<P2_NBLK, 256, P2_SMEM>>>(Wh, bh, out);
}